// round 1
// baseline (speedup 1.0000x reference)
#include <cuda_runtime.h>
#include <math.h>

// ---------------- problem constants ----------------
#define BB 16384      // batch
#define FF 26         // onehot fields
#define EE 32         // embedding dim
#define LL 50         // bag length
#define D0 909
#define D1 512
#define D2 256
#define XS 928        // D0 padded to multiple of 16 (zero-filled tail)

// ---------------- scratch (static device globals: allocation-free) ----------
__device__ float g_X  [(size_t)BB * XS];   // 60.8 MB activation matrix
__device__ float g_W2p[(size_t)D1 * XS];   // 1.9 MB padded w2
__device__ float g_H1 [(size_t)BB * D1];   // 33.5 MB
__device__ float g_H2 [(size_t)BB * D2];   // 16.8 MB
__device__ float g_wide[BB];

// ---------------- w2 pad/copy: [D1,909] -> [D1,928] zero tail ---------------
__global__ void pad_w2_kernel(const float* __restrict__ w2, float* __restrict__ W2p) {
    int n = blockIdx.x;
    for (int k = threadIdx.x; k < XS; k += blockDim.x)
        W2p[(size_t)n * XS + k] = (k < D0) ? w2[(size_t)n * D0 + k] : 0.0f;
}

// ---------------- gather: build X[B,928] and wide_sum[B] --------------------
// One block (128 thr = 4 warps) per batch row.
__global__ __launch_bounds__(128) void gather_kernel(
    const int*   __restrict__ oh_i,  const float* __restrict__ oh_x,
    const int*   __restrict__ mi1,   const float* __restrict__ mx1,
    const int*   __restrict__ mi2,   const float* __restrict__ mx2,
    const float* __restrict__ ctns,
    const float* __restrict__ wideT, const float* __restrict__ deepT,
    float* __restrict__ X, float* __restrict__ wide_out)
{
    const int row  = blockIdx.x;
    const int tid  = threadIdx.x;
    const int warp = tid >> 5;
    const int lane = tid & 31;
    float* xr = X + (size_t)row * XS;

    // onehot fields: warp w handles f = w, w+4, ... ; lane = embedding dim
    for (int f = warp; f < FF; f += 4) {
        int   idx = oh_i[row * FF + f];
        float w   = oh_x[row * FF + f];
        xr[f * EE + lane] = deepT[(size_t)idx * EE + lane] * w;
    }

    // multihot bags: warps 0,1 -> bag1 (odd/even j), warps 2,3 -> bag2
    {
        const int*   mi = (warp < 2) ? mi1 : mi2;
        const float* mx = (warp < 2) ? mx1 : mx2;
        const int half  = warp & 1;
        float acc = 0.0f;
        for (int j = half; j < LL; j += 2) {
            int   idx = mi[row * LL + j];
            float w   = mx[row * LL + j];
            acc += deepT[(size_t)idx * EE + lane] * w;
        }
        __shared__ float sb[4][EE];
        sb[warp][lane] = acc;
        __syncthreads();
        if      (warp == 0) xr[FF * EE      + lane] = sb[0][lane] + sb[1][lane];
        else if (warp == 1) xr[FF * EE + EE + lane] = sb[2][lane] + sb[3][lane];
        else if (warp == 2) { if (lane < 13) xr[FF * EE + 2 * EE + lane] = ctns[row * 13 + lane]; }
        else                { if (lane < XS - D0) xr[D0 + lane] = 0.0f; }  // zero pad tail
    }

    // wide part: 126 scalar gathers spread over the 128 threads
    float wv = 0.0f;
    if (tid < FF) {
        wv = wideT[oh_i[row * FF + tid]] * oh_x[row * FF + tid];
    } else if (tid < FF + LL) {
        int j = tid - FF;
        wv = wideT[mi1[row * LL + j]] * mx1[row * LL + j];
    } else if (tid < FF + 2 * LL) {
        int j = tid - FF - LL;
        wv = wideT[mi2[row * LL + j]] * mx2[row * LL + j];
    }
    #pragma unroll
    for (int o = 16; o; o >>= 1) wv += __shfl_xor_sync(0xFFFFFFFFu, wv, o);
    __shared__ float swide[4];
    if (lane == 0) swide[warp] = wv;
    __syncthreads();
    if (tid == 0)
        wide_out[row] = swide[0] + swide[1] + swide[2] + swide[3];
}

// ---------------- FP32 register-tiled GEMM: C = A(M,K) * B(N,K)^T -----------
// bias + leaky-relu epilogue. K, lda, ldb, ldc must be multiples of 4;
// M % BM == 0, N % BN == 0, K % BK == 0 (guaranteed by padding).
template <int BM, int BN, int BK, int TM, int TN>
__global__ void __launch_bounds__(256) sgemm_nt_bias_leaky(
    const float* __restrict__ A, int lda,
    const float* __restrict__ B, int ldb,
    const float* __restrict__ bias,
    float* __restrict__ C, int ldc, int K)
{
    __shared__ float As[BK][BM + 4];
    __shared__ float Bs[BK][BN + 4];

    const int tid = threadIdx.x;
    const int tx  = tid & (BN / TN - 1);        // 0..15
    const int ty  = tid / (BN / TN);            // 0..15
    const int bm  = blockIdx.y * BM;
    const int bn  = blockIdx.x * BN;

    const int lr = tid >> 2;                    // 0..63 loader row
    const int lc = (tid & 3) * 4;               // 0,4,8,12 loader col

    float acc[TM][TN];
    #pragma unroll
    for (int i = 0; i < TM; i++)
        #pragma unroll
        for (int j = 0; j < TN; j++) acc[i][j] = 0.0f;

    for (int k0 = 0; k0 < K; k0 += BK) {
        // A tile: BM x BK, stored transposed As[k][m]
        #pragma unroll
        for (int t = 0; t < BM / 64; t++) {
            int r = lr + t * 64;
            float4 v = *reinterpret_cast<const float4*>(
                &A[(size_t)(bm + r) * lda + k0 + lc]);
            As[lc + 0][r] = v.x; As[lc + 1][r] = v.y;
            As[lc + 2][r] = v.z; As[lc + 3][r] = v.w;
        }
        // B tile: BN x BK, stored transposed Bs[k][n]
        #pragma unroll
        for (int t = 0; t < BN / 64; t++) {
            int r = lr + t * 64;
            float4 v = *reinterpret_cast<const float4*>(
                &B[(size_t)(bn + r) * ldb + k0 + lc]);
            Bs[lc + 0][r] = v.x; Bs[lc + 1][r] = v.y;
            Bs[lc + 2][r] = v.z; Bs[lc + 3][r] = v.w;
        }
        __syncthreads();

        #pragma unroll
        for (int k = 0; k < BK; k++) {
            float ar[TM], br[TN];
            #pragma unroll
            for (int i = 0; i < TM; i += 4) {
                float4 v = *reinterpret_cast<const float4*>(&As[k][ty * TM + i]);
                ar[i] = v.x; ar[i + 1] = v.y; ar[i + 2] = v.z; ar[i + 3] = v.w;
            }
            #pragma unroll
            for (int j = 0; j < TN; j += 4) {
                float4 v = *reinterpret_cast<const float4*>(&Bs[k][tx * TN + j]);
                br[j] = v.x; br[j + 1] = v.y; br[j + 2] = v.z; br[j + 3] = v.w;
            }
            #pragma unroll
            for (int i = 0; i < TM; i++)
                #pragma unroll
                for (int j = 0; j < TN; j++)
                    acc[i][j] = fmaf(ar[i], br[j], acc[i][j]);
        }
        __syncthreads();
    }

    // epilogue: bias + leaky, vectorized store (TN == 4)
    #pragma unroll
    for (int i = 0; i < TM; i++) {
        int m = bm + ty * TM + i;
        float4 o;
        float* po = &o.x;
        #pragma unroll
        for (int j = 0; j < TN; j++) {
            int n = bn + tx * TN + j;
            float v = acc[i][j] + bias[n];
            po[j] = (v >= 0.0f) ? v : 0.01f * v;
        }
        *reinterpret_cast<float4*>(&C[(size_t)m * ldc + bn + tx * TN]) = o;
    }
}

// ---------------- final: out = sigmoid(H2 . w4 + b4 + 32*wide) --------------
// 8 warps/block, one row per warp.
__global__ __launch_bounds__(256) void final_kernel(
    const float* __restrict__ H2, const float* __restrict__ w4,
    const float* __restrict__ b4, const float* __restrict__ wide,
    float* __restrict__ out)
{
    __shared__ float sw4[D2];
    int tid = threadIdx.x;
    sw4[tid] = w4[tid];
    __syncthreads();

    int warp = tid >> 5, lane = tid & 31;
    int row  = blockIdx.x * 8 + warp;
    const float* h = H2 + (size_t)row * D2;
    float acc = 0.0f;
    #pragma unroll
    for (int i = 0; i < D2 / 32; i++)
        acc += h[lane + i * 32] * sw4[lane + i * 32];
    #pragma unroll
    for (int o = 16; o; o >>= 1) acc += __shfl_xor_sync(0xFFFFFFFFu, acc, o);
    if (lane == 0) {
        float z = acc + b4[0] + (float)EE * wide[row];
        out[row] = 1.0f / (1.0f + expf(-z));
    }
}

// ---------------- launch ----------------------------------------------------
extern "C" void kernel_launch(void* const* d_in, const int* in_sizes, int n_in,
                              void* d_out, int out_size)
{
    const int*   oh_i  = (const int*)  d_in[0];
    const float* oh_x  = (const float*)d_in[1];
    const int*   mi1   = (const int*)  d_in[2];
    const float* mx1   = (const float*)d_in[3];
    const int*   mi2   = (const int*)  d_in[4];
    const float* mx2   = (const float*)d_in[5];
    const float* ctns  = (const float*)d_in[6];
    const float* wideT = (const float*)d_in[7];
    const float* deepT = (const float*)d_in[8];
    const float* w2    = (const float*)d_in[9];
    const float* b2    = (const float*)d_in[10];
    const float* w3    = (const float*)d_in[11];
    const float* b3    = (const float*)d_in[12];
    const float* w4    = (const float*)d_in[13];
    const float* b4    = (const float*)d_in[14];
    float* out = (float*)d_out;

    float *X, *W2p, *H1, *H2, *wide;
    cudaGetSymbolAddress((void**)&X,    g_X);
    cudaGetSymbolAddress((void**)&W2p,  g_W2p);
    cudaGetSymbolAddress((void**)&H1,   g_H1);
    cudaGetSymbolAddress((void**)&H2,   g_H2);
    cudaGetSymbolAddress((void**)&wide, g_wide);

    pad_w2_kernel<<<D1, 256>>>(w2, W2p);
    gather_kernel<<<BB, 128>>>(oh_i, oh_x, mi1, mx1, mi2, mx2, ctns,
                               wideT, deepT, X, wide);

    // layer 1: [B,928(909)] x [512,928]^T -> H1[B,512]
    sgemm_nt_bias_leaky<128, 64, 16, 8, 4>
        <<<dim3(D1 / 64, BB / 128), 256>>>(X, XS, W2p, XS, b2, H1, D1, XS);

    // layer 2: [B,512] x [256,512]^T -> H2[B,256]
    sgemm_nt_bias_leaky<128, 64, 16, 8, 4>
        <<<dim3(D2 / 64, BB / 128), 256>>>(H1, D1, w3, D1, b3, H2, D2, D1);

    // layer 3 + wide + sigmoid
    final_kernel<<<BB / 8, 256>>>(H2, w4, b4, wide, out);
}

// round 3
// speedup vs baseline: 2.0207x; 2.0207x over previous
#include <cuda_runtime.h>
#include <math.h>
#include <stdint.h>

// ---------------- problem constants ----------------
#define BB 16384      // batch
#define FF 26         // onehot fields
#define EE 32         // embedding dim
#define LL 50         // bag length
#define D0 909
#define D1 512
#define D2 256
#define XS 928        // D0 padded to multiple of 16 (zero-filled tail)

// ---------------- scratch (static device globals: allocation-free) ----------
__device__ float g_X  [(size_t)BB * XS];   // activations (tf32-rounded)
__device__ float g_W2p[(size_t)D1 * XS];   // padded + tf32-rounded w2
__device__ float g_W3r[(size_t)D2 * D1];   // tf32-rounded w3
__device__ float g_H1 [(size_t)BB * D1];   // layer-1 out (tf32-rounded)
__device__ float g_H2 [(size_t)BB * D2];   // layer-2 out (fp32)
__device__ float g_wide[BB];

// ---------------- helpers ----------------------------------------------------
// tf32 round: PTX cvt to tf32 requires a .b32 destination register.
__device__ __forceinline__ float tf32r(float x) {
    uint32_t y;
    asm("cvt.rna.tf32.f32 %0, %1;" : "=r"(y) : "f"(x));
    return __uint_as_float(y);
}

#define CP16(dst, src) \
    asm volatile("cp.async.cg.shared.global [%0], [%1], 16;\n" :: "r"(dst), "l"(src))
#define CPCOMMIT() asm volatile("cp.async.commit_group;\n" ::)
#define CPWAIT0()  asm volatile("cp.async.wait_group 0;\n" ::)

__device__ __forceinline__ void mma_tf32(
    float* d, const uint32_t* a, const uint32_t* b)
{
    asm volatile(
        "mma.sync.aligned.m16n8k8.row.col.f32.tf32.tf32.f32 "
        "{%0,%1,%2,%3}, {%4,%5,%6,%7}, {%8,%9}, {%0,%1,%2,%3};"
        : "+f"(d[0]), "+f"(d[1]), "+f"(d[2]), "+f"(d[3])
        : "r"(a[0]), "r"(a[1]), "r"(a[2]), "r"(a[3]),
          "r"(b[0]), "r"(b[1]));
}

// ---------------- weight prep: pad/round w2, round w3 -----------------------
__global__ void prep_weights(const float* __restrict__ w2,
                             const float* __restrict__ w3,
                             float* __restrict__ W2p,
                             float* __restrict__ W3r)
{
    int n = blockIdx.x;
    if (n < D1) {
        for (int k = threadIdx.x; k < XS; k += blockDim.x)
            W2p[(size_t)n * XS + k] = (k < D0) ? tf32r(w2[(size_t)n * D0 + k]) : 0.0f;
    } else {
        int m = n - D1;
        for (int k = threadIdx.x; k < D1; k += blockDim.x)
            W3r[(size_t)m * D1 + k] = tf32r(w3[(size_t)m * D1 + k]);
    }
}

// ---------------- gather: build X[B,928] (tf32-rounded) + wide_sum[B] -------
__global__ __launch_bounds__(128) void gather_kernel(
    const int*   __restrict__ oh_i,  const float* __restrict__ oh_x,
    const int*   __restrict__ mi1,   const float* __restrict__ mx1,
    const int*   __restrict__ mi2,   const float* __restrict__ mx2,
    const float* __restrict__ ctns,
    const float* __restrict__ wideT, const float* __restrict__ deepT,
    float* __restrict__ X, float* __restrict__ wide_out)
{
    const int row  = blockIdx.x;
    const int tid  = threadIdx.x;
    const int warp = tid >> 5;
    const int lane = tid & 31;
    float* xr = X + (size_t)row * XS;

    for (int f = warp; f < FF; f += 4) {
        int   idx = oh_i[row * FF + f];
        float w   = oh_x[row * FF + f];
        xr[f * EE + lane] = tf32r(deepT[(size_t)idx * EE + lane] * w);
    }

    {
        const int*   mi = (warp < 2) ? mi1 : mi2;
        const float* mx = (warp < 2) ? mx1 : mx2;
        const int half  = warp & 1;
        float acc = 0.0f;
        for (int j = half; j < LL; j += 2) {
            int   idx = mi[row * LL + j];
            float w   = mx[row * LL + j];
            acc += deepT[(size_t)idx * EE + lane] * w;
        }
        __shared__ float sb[4][EE];
        sb[warp][lane] = acc;
        __syncthreads();
        if      (warp == 0) xr[FF * EE      + lane] = tf32r(sb[0][lane] + sb[1][lane]);
        else if (warp == 1) xr[FF * EE + EE + lane] = tf32r(sb[2][lane] + sb[3][lane]);
        else if (warp == 2) { if (lane < 13) xr[FF * EE + 2 * EE + lane] = tf32r(ctns[row * 13 + lane]); }
        else                { if (lane < XS - D0) xr[D0 + lane] = 0.0f; }
    }

    float wv = 0.0f;
    if (tid < FF) {
        wv = wideT[oh_i[row * FF + tid]] * oh_x[row * FF + tid];
    } else if (tid < FF + LL) {
        int j = tid - FF;
        wv = wideT[mi1[row * LL + j]] * mx1[row * LL + j];
    } else if (tid < FF + 2 * LL) {
        int j = tid - FF - LL;
        wv = wideT[mi2[row * LL + j]] * mx2[row * LL + j];
    }
    #pragma unroll
    for (int o = 16; o; o >>= 1) wv += __shfl_xor_sync(0xFFFFFFFFu, wv, o);
    __shared__ float swide[4];
    if (lane == 0) swide[warp] = wv;
    __syncthreads();
    if (tid == 0)
        wide_out[row] = swide[0] + swide[1] + swide[2] + swide[3];
}

// ---------------- TF32 tensor-core GEMM: C = A(M,K) * B(N,K)^T --------------
// block tile 128x64, BK=16, 8 warps as 4(M) x 2(N), warp tile 32x32.
// A, B pre-rounded to tf32 by producers. bias + leaky epilogue;
// ROUND rounds the output to tf32 (feeds the next tf32 GEMM).
template <bool ROUND>
__global__ void __launch_bounds__(256) tf32_gemm(
    const float* __restrict__ A, int lda,
    const float* __restrict__ Bm, int ldb,
    const float* __restrict__ bias,
    float* __restrict__ C, int ldc, int K)
{
    constexpr int BM = 128, BN = 64, BK = 16, LDS = BK + 4;  // stride 20: conflict-free frags
    __shared__ float As[2][BM][LDS];
    __shared__ float Bs[2][BN][LDS];

    const int tid  = threadIdx.x;
    const int warp = tid >> 5;
    const int lane = tid & 31;
    const int wm = (warp >> 1) * 32;   // 4 warps in M
    const int wn = (warp & 1) * 32;    // 2 warps in N
    const int r  = lane >> 2;          // 0..7
    const int c  = lane & 3;           // 0..3

    const int bm = blockIdx.y * BM;
    const int bn = blockIdx.x * BN;

    // loader coords: each thread owns one 16B chunk per tile row-group
    const int arow = tid >> 2;         // 0..63
    const int acol = (tid & 3) * 4;    // 0,4,8,12
    const float* gA0 = A  + (size_t)(bm + arow)      * lda + acol;
    const float* gA1 = A  + (size_t)(bm + arow + 64) * lda + acol;
    const float* gB  = Bm + (size_t)(bn + arow)      * ldb + acol;

    uint32_t sA0[2], sA1[2], sB0[2];
    #pragma unroll
    for (int bbuf = 0; bbuf < 2; bbuf++) {
        sA0[bbuf] = (uint32_t)__cvta_generic_to_shared(&As[bbuf][arow][acol]);
        sA1[bbuf] = (uint32_t)__cvta_generic_to_shared(&As[bbuf][arow + 64][acol]);
        sB0[bbuf] = (uint32_t)__cvta_generic_to_shared(&Bs[bbuf][arow][acol]);
    }

    float acc[2][4][4];
    #pragma unroll
    for (int i = 0; i < 2; i++)
        #pragma unroll
        for (int j = 0; j < 4; j++)
            #pragma unroll
            for (int q = 0; q < 4; q++) acc[i][j][q] = 0.0f;

    const int T = K / BK;

    // prologue: load tile 0 into buffer 0
    CP16(sA0[0], gA0);
    CP16(sA1[0], gA1);
    CP16(sB0[0], gB);
    CPCOMMIT();

    int buf = 0;
    for (int t = 0; t < T; t++) {
        CPWAIT0();
        __syncthreads();   // tile t visible; all threads done with buf^1

        if (t + 1 < T) {
            int k0 = (t + 1) * BK;
            CP16(sA0[buf ^ 1], gA0 + k0);
            CP16(sA1[buf ^ 1], gA1 + k0);
            CP16(sB0[buf ^ 1], gB  + k0);
            CPCOMMIT();
        }

        #pragma unroll
        for (int kk = 0; kk < BK; kk += 8) {
            uint32_t af[2][4], bf[4][2];
            #pragma unroll
            for (int i = 0; i < 2; i++) {
                const int m0 = wm + 16 * i;
                af[i][0] = __float_as_uint(As[buf][m0 + r    ][kk + c    ]);
                af[i][1] = __float_as_uint(As[buf][m0 + r + 8][kk + c    ]);
                af[i][2] = __float_as_uint(As[buf][m0 + r    ][kk + c + 4]);
                af[i][3] = __float_as_uint(As[buf][m0 + r + 8][kk + c + 4]);
            }
            #pragma unroll
            for (int j = 0; j < 4; j++) {
                const int n0 = wn + 8 * j;
                bf[j][0] = __float_as_uint(Bs[buf][n0 + r][kk + c    ]);
                bf[j][1] = __float_as_uint(Bs[buf][n0 + r][kk + c + 4]);
            }
            #pragma unroll
            for (int i = 0; i < 2; i++)
                #pragma unroll
                for (int j = 0; j < 4; j++)
                    mma_tf32(acc[i][j], af[i], bf[j]);
        }
        buf ^= 1;
    }

    // epilogue: bias + leaky (+ optional tf32 round), float2 stores
    #pragma unroll
    for (int i = 0; i < 2; i++) {
        #pragma unroll
        for (int j = 0; j < 4; j++) {
            const int n0 = bn + wn + 8 * j + c * 2;
            const float bi0 = __ldg(&bias[n0]);
            const float bi1 = __ldg(&bias[n0 + 1]);
            #pragma unroll
            for (int h = 0; h < 2; h++) {
                const int m = bm + wm + 16 * i + r + 8 * h;
                float v0 = acc[i][j][2 * h + 0] + bi0;
                float v1 = acc[i][j][2 * h + 1] + bi1;
                v0 = (v0 >= 0.0f) ? v0 : 0.01f * v0;
                v1 = (v1 >= 0.0f) ? v1 : 0.01f * v1;
                if (ROUND) { v0 = tf32r(v0); v1 = tf32r(v1); }
                float2 o = make_float2(v0, v1);
                *reinterpret_cast<float2*>(&C[(size_t)m * ldc + n0]) = o;
            }
        }
    }
}

// ---------------- final: out = sigmoid(H2 . w4 + b4 + 32*wide) --------------
__global__ __launch_bounds__(256) void final_kernel(
    const float* __restrict__ H2, const float* __restrict__ w4,
    const float* __restrict__ b4, const float* __restrict__ wide,
    float* __restrict__ out)
{
    __shared__ float sw4[D2];
    int tid = threadIdx.x;
    sw4[tid] = w4[tid];
    __syncthreads();

    int warp = tid >> 5, lane = tid & 31;
    int row  = blockIdx.x * 8 + warp;
    const float* h = H2 + (size_t)row * D2;
    float acc = 0.0f;
    #pragma unroll
    for (int i = 0; i < D2 / 32; i++)
        acc += h[lane + i * 32] * sw4[lane + i * 32];
    #pragma unroll
    for (int o = 16; o; o >>= 1) acc += __shfl_xor_sync(0xFFFFFFFFu, acc, o);
    if (lane == 0) {
        float z = acc + b4[0] + (float)EE * wide[row];
        out[row] = 1.0f / (1.0f + expf(-z));
    }
}

// ---------------- launch ----------------------------------------------------
extern "C" void kernel_launch(void* const* d_in, const int* in_sizes, int n_in,
                              void* d_out, int out_size)
{
    const int*   oh_i  = (const int*)  d_in[0];
    const float* oh_x  = (const float*)d_in[1];
    const int*   mi1   = (const int*)  d_in[2];
    const float* mx1   = (const float*)d_in[3];
    const int*   mi2   = (const int*)  d_in[4];
    const float* mx2   = (const float*)d_in[5];
    const float* ctns  = (const float*)d_in[6];
    const float* wideT = (const float*)d_in[7];
    const float* deepT = (const float*)d_in[8];
    const float* w2    = (const float*)d_in[9];
    const float* b2    = (const float*)d_in[10];
    const float* w3    = (const float*)d_in[11];
    const float* b3    = (const float*)d_in[12];
    const float* w4    = (const float*)d_in[13];
    const float* b4    = (const float*)d_in[14];
    float* out = (float*)d_out;

    float *X, *W2p, *W3r, *H1, *H2, *wide;
    cudaGetSymbolAddress((void**)&X,    g_X);
    cudaGetSymbolAddress((void**)&W2p,  g_W2p);
    cudaGetSymbolAddress((void**)&W3r,  g_W3r);
    cudaGetSymbolAddress((void**)&H1,   g_H1);
    cudaGetSymbolAddress((void**)&H2,   g_H2);
    cudaGetSymbolAddress((void**)&wide, g_wide);

    prep_weights<<<D1 + D2, 256>>>(w2, w3, W2p, W3r);
    gather_kernel<<<BB, 128>>>(oh_i, oh_x, mi1, mx1, mi2, mx2, ctns,
                               wideT, deepT, X, wide);

    // layer 1: [B,928] x [512,928]^T -> H1[B,512]   (tf32, round output)
    tf32_gemm<true>
        <<<dim3(D1 / 64, BB / 128), 256>>>(X, XS, W2p, XS, b2, H1, D1, XS);

    // layer 2: [B,512] x [256,512]^T -> H2[B,256]   (tf32, fp32 output)
    tf32_gemm<false>
        <<<dim3(D2 / 64, BB / 128), 256>>>(H1, D1, W3r, D1, b3, H2, D2, D1);

    // layer 3 + wide + sigmoid
    final_kernel<<<BB / 8, 256>>>(H2, w4, b4, wide, out);
}

// round 4
// speedup vs baseline: 3.0884x; 1.5284x over previous
#include <cuda_runtime.h>
#include <cuda_bf16.h>
#include <math.h>
#include <stdint.h>

// ---------------- problem constants ----------------
#define BB 16384      // batch
#define FF 26         // onehot fields
#define EE 32         // embedding dim
#define LL 50         // bag length
#define D0 909
#define D1 512
#define D2 256
#define XS 928        // D0 padded (zero tail), multiple of 32

// ---------------- scratch (static device globals: allocation-free) ----------
__device__ __nv_bfloat16 g_X  [(size_t)BB * XS];   // activations bf16
__device__ __nv_bfloat16 g_W2p[(size_t)D1 * XS];   // padded w2 bf16
__device__ __nv_bfloat16 g_W3r[(size_t)D2 * D1];   // w3 bf16
__device__ __nv_bfloat16 g_H1 [(size_t)BB * D1];   // layer-1 out bf16
__device__ float         g_H2 [(size_t)BB * D2];   // layer-2 out fp32
__device__ float         g_wide[BB];

// ---------------- helpers ----------------------------------------------------
#define CP16(dst, src) \
    asm volatile("cp.async.cg.shared.global [%0], [%1], 16;\n" :: "r"(dst), "l"(src))
#define CPCOMMIT() asm volatile("cp.async.commit_group;\n" ::)
#define CPWAIT0()  asm volatile("cp.async.wait_group 0;\n" ::)

__device__ __forceinline__ void ldsm_x4(uint32_t* r, uint32_t addr) {
    asm volatile("ldmatrix.sync.aligned.m8n8.x4.shared.b16 {%0,%1,%2,%3}, [%4];"
                 : "=r"(r[0]), "=r"(r[1]), "=r"(r[2]), "=r"(r[3]) : "r"(addr));
}

__device__ __forceinline__ void mma_bf16(float* d, const uint32_t* a, const uint32_t* b) {
    asm volatile(
        "mma.sync.aligned.m16n8k16.row.col.f32.bf16.bf16.f32 "
        "{%0,%1,%2,%3}, {%4,%5,%6,%7}, {%8,%9}, {%0,%1,%2,%3};"
        : "+f"(d[0]), "+f"(d[1]), "+f"(d[2]), "+f"(d[3])
        : "r"(a[0]), "r"(a[1]), "r"(a[2]), "r"(a[3]), "r"(b[0]), "r"(b[1]));
}

// ---------------- weight prep: pad/convert w2, convert w3 -------------------
__global__ void prep_weights(const float* __restrict__ w2,
                             const float* __restrict__ w3,
                             __nv_bfloat16* __restrict__ W2p,
                             __nv_bfloat16* __restrict__ W3r)
{
    int n = blockIdx.x;
    if (n < D1) {
        for (int k = threadIdx.x; k < XS; k += blockDim.x)
            W2p[(size_t)n * XS + k] = (k < D0) ? __float2bfloat16_rn(w2[(size_t)n * D0 + k])
                                               : __float2bfloat16_rn(0.0f);
    } else {
        int m = n - D1;
        for (int k = threadIdx.x; k < D1; k += blockDim.x)
            W3r[(size_t)m * D1 + k] = __float2bfloat16_rn(w3[(size_t)m * D1 + k]);
    }
}

// ---------------- gather: build X[B,928] (bf16) + wide_sum[B] ---------------
__global__ __launch_bounds__(128) void gather_kernel(
    const int*   __restrict__ oh_i,  const float* __restrict__ oh_x,
    const int*   __restrict__ mi1,   const float* __restrict__ mx1,
    const int*   __restrict__ mi2,   const float* __restrict__ mx2,
    const float* __restrict__ ctns,
    const float* __restrict__ wideT, const float* __restrict__ deepT,
    __nv_bfloat16* __restrict__ X, float* __restrict__ wide_out)
{
    const int row  = blockIdx.x;
    const int tid  = threadIdx.x;
    const int warp = tid >> 5;
    const int lane = tid & 31;
    __nv_bfloat16* xr = X + (size_t)row * XS;

    for (int f = warp; f < FF; f += 4) {
        int   idx = oh_i[row * FF + f];
        float w   = oh_x[row * FF + f];
        xr[f * EE + lane] = __float2bfloat16_rn(deepT[(size_t)idx * EE + lane] * w);
    }

    {
        const int*   mi = (warp < 2) ? mi1 : mi2;
        const float* mx = (warp < 2) ? mx1 : mx2;
        const int half  = warp & 1;
        float acc = 0.0f;
        for (int j = half; j < LL; j += 2) {
            int   idx = mi[row * LL + j];
            float w   = mx[row * LL + j];
            acc += deepT[(size_t)idx * EE + lane] * w;
        }
        __shared__ float sb[4][EE];
        sb[warp][lane] = acc;
        __syncthreads();
        if      (warp == 0) xr[FF * EE      + lane] = __float2bfloat16_rn(sb[0][lane] + sb[1][lane]);
        else if (warp == 1) xr[FF * EE + EE + lane] = __float2bfloat16_rn(sb[2][lane] + sb[3][lane]);
        else if (warp == 2) { if (lane < 13) xr[FF * EE + 2 * EE + lane] = __float2bfloat16_rn(ctns[row * 13 + lane]); }
        else                { if (lane < XS - D0) xr[D0 + lane] = __float2bfloat16_rn(0.0f); }
    }

    float wv = 0.0f;
    if (tid < FF) {
        wv = wideT[oh_i[row * FF + tid]] * oh_x[row * FF + tid];
    } else if (tid < FF + LL) {
        int j = tid - FF;
        wv = wideT[mi1[row * LL + j]] * mx1[row * LL + j];
    } else if (tid < FF + 2 * LL) {
        int j = tid - FF - LL;
        wv = wideT[mi2[row * LL + j]] * mx2[row * LL + j];
    }
    #pragma unroll
    for (int o = 16; o; o >>= 1) wv += __shfl_xor_sync(0xFFFFFFFFu, wv, o);
    __shared__ float swide[4];
    if (lane == 0) swide[warp] = wv;
    __syncthreads();
    if (tid == 0)
        wide_out[row] = swide[0] + swide[1] + swide[2] + swide[3];
}

// ---------------- bf16 tensor-core GEMM: C = A(M,K) * B(N,K)^T --------------
// block 128x64, BK=32, 8 warps 4(M)x2(N), warp tile 32x32.
// ldmatrix.x4 fragment loads, cp.async double buffer.
// Smem row stride 40 bf16 (80 B): 8-row ldmatrix groups hit disjoint bank sets.
template <bool OUT_BF16>
__global__ void __launch_bounds__(256) bf16_gemm(
    const __nv_bfloat16* __restrict__ A, int lda,
    const __nv_bfloat16* __restrict__ Bm, int ldb,
    const float* __restrict__ bias,
    void* __restrict__ Cv, int ldc, int K)
{
    constexpr int BM = 128, BN = 64, BK = 32, LDA = BK + 8;  // 40 bf16 = 80 B stride
    __shared__ alignas(16) __nv_bfloat16 As[2][BM][LDA];
    __shared__ alignas(16) __nv_bfloat16 Bs[2][BN][LDA];

    const int tid  = threadIdx.x;
    const int warp = tid >> 5;
    const int lane = tid & 31;
    const int wm = (warp >> 1) * 32;   // 4 warps in M
    const int wn = (warp & 1) * 32;    // 2 warps in N
    const int r  = lane >> 2;          // 0..7
    const int c  = lane & 3;           // 0..3

    const int bm = blockIdx.y * BM;
    const int bn = blockIdx.x * BN;

    // cp.async loader coords: 16B = 8 bf16 per chunk
    const int lrow = tid >> 2;          // 0..63
    const int lcol = (tid & 3) * 8;     // 0,8,16,24
    const __nv_bfloat16* gA0 = A  + (size_t)(bm + lrow)      * lda + lcol;
    const __nv_bfloat16* gA1 = A  + (size_t)(bm + lrow + 64) * lda + lcol;
    const __nv_bfloat16* gB  = Bm + (size_t)(bn + lrow)      * ldb + lcol;

    uint32_t sA0[2], sA1[2], sB0[2];
    #pragma unroll
    for (int bbuf = 0; bbuf < 2; bbuf++) {
        sA0[bbuf] = (uint32_t)__cvta_generic_to_shared(&As[bbuf][lrow][lcol]);
        sA1[bbuf] = (uint32_t)__cvta_generic_to_shared(&As[bbuf][lrow + 64][lcol]);
        sB0[bbuf] = (uint32_t)__cvta_generic_to_shared(&Bs[bbuf][lrow][lcol]);
    }

    // ldmatrix lane address mapping
    const int rowA_l = lane & 15;                    // row within 16-row frag
    const int colA_l = (lane >> 4) << 3;             // 0 or 8
    const int rowB_l = (lane & 7) + ((lane & 16) >> 1);  // n within 16
    const int colB_l = lane & 8;                     // 0 or 8
    uint32_t aBase[2], bBase[2];
    #pragma unroll
    for (int bbuf = 0; bbuf < 2; bbuf++) {
        aBase[bbuf] = (uint32_t)__cvta_generic_to_shared(&As[bbuf][wm + rowA_l][colA_l]);
        bBase[bbuf] = (uint32_t)__cvta_generic_to_shared(&Bs[bbuf][wn + rowB_l][colB_l]);
    }

    float acc[2][4][4];
    #pragma unroll
    for (int i = 0; i < 2; i++)
        #pragma unroll
        for (int j = 0; j < 4; j++)
            #pragma unroll
            for (int q = 0; q < 4; q++) acc[i][j][q] = 0.0f;

    const int T = K / BK;

    // prologue
    CP16(sA0[0], gA0);
    CP16(sA1[0], gA1);
    CP16(sB0[0], gB);
    CPCOMMIT();

    int buf = 0;
    for (int t = 0; t < T; t++) {
        CPWAIT0();
        __syncthreads();

        if (t + 1 < T) {
            int k0 = (t + 1) * BK;
            CP16(sA0[buf ^ 1], gA0 + k0);
            CP16(sA1[buf ^ 1], gA1 + k0);
            CP16(sB0[buf ^ 1], gB  + k0);
            CPCOMMIT();
        }

        #pragma unroll
        for (int kk = 0; kk < BK; kk += 16) {
            uint32_t af[2][4], bq[2][4];
            #pragma unroll
            for (int i = 0; i < 2; i++)
                ldsm_x4(af[i], aBase[buf] + (uint32_t)((16 * i * LDA + kk) * 2));
            #pragma unroll
            for (int j16 = 0; j16 < 2; j16++)
                ldsm_x4(bq[j16], bBase[buf] + (uint32_t)((16 * j16 * LDA + kk) * 2));
            #pragma unroll
            for (int i = 0; i < 2; i++)
                #pragma unroll
                for (int j = 0; j < 4; j++)
                    mma_bf16(acc[i][j], af[i], &bq[j >> 1][(j & 1) * 2]);
        }
        buf ^= 1;
    }

    // epilogue: bias + leaky
    #pragma unroll
    for (int i = 0; i < 2; i++) {
        #pragma unroll
        for (int j = 0; j < 4; j++) {
            const int n0 = bn + wn + 8 * j + c * 2;
            const float bi0 = __ldg(&bias[n0]);
            const float bi1 = __ldg(&bias[n0 + 1]);
            #pragma unroll
            for (int h = 0; h < 2; h++) {
                const int m = bm + wm + 16 * i + r + 8 * h;
                float v0 = acc[i][j][2 * h + 0] + bi0;
                float v1 = acc[i][j][2 * h + 1] + bi1;
                v0 = (v0 >= 0.0f) ? v0 : 0.01f * v0;
                v1 = (v1 >= 0.0f) ? v1 : 0.01f * v1;
                if (OUT_BF16) {
                    __nv_bfloat162 o = make_bfloat162(__float2bfloat16_rn(v0),
                                                      __float2bfloat16_rn(v1));
                    *reinterpret_cast<__nv_bfloat162*>(
                        &((__nv_bfloat16*)Cv)[(size_t)m * ldc + n0]) = o;
                } else {
                    float2 o = make_float2(v0, v1);
                    *reinterpret_cast<float2*>(&((float*)Cv)[(size_t)m * ldc + n0]) = o;
                }
            }
        }
    }
}

// ---------------- final: out = sigmoid(H2 . w4 + b4 + 32*wide) --------------
__global__ __launch_bounds__(256) void final_kernel(
    const float* __restrict__ H2, const float* __restrict__ w4,
    const float* __restrict__ b4, const float* __restrict__ wide,
    float* __restrict__ out)
{
    __shared__ float sw4[D2];
    int tid = threadIdx.x;
    sw4[tid] = w4[tid];
    __syncthreads();

    int warp = tid >> 5, lane = tid & 31;
    int row  = blockIdx.x * 8 + warp;
    const float* h = H2 + (size_t)row * D2;
    float acc = 0.0f;
    #pragma unroll
    for (int i = 0; i < D2 / 32; i++)
        acc += h[lane + i * 32] * sw4[lane + i * 32];
    #pragma unroll
    for (int o = 16; o; o >>= 1) acc += __shfl_xor_sync(0xFFFFFFFFu, acc, o);
    if (lane == 0) {
        float z = acc + b4[0] + (float)EE * wide[row];
        out[row] = 1.0f / (1.0f + expf(-z));
    }
}

// ---------------- launch ----------------------------------------------------
extern "C" void kernel_launch(void* const* d_in, const int* in_sizes, int n_in,
                              void* d_out, int out_size)
{
    const int*   oh_i  = (const int*)  d_in[0];
    const float* oh_x  = (const float*)d_in[1];
    const int*   mi1   = (const int*)  d_in[2];
    const float* mx1   = (const float*)d_in[3];
    const int*   mi2   = (const int*)  d_in[4];
    const float* mx2   = (const float*)d_in[5];
    const float* ctns  = (const float*)d_in[6];
    const float* wideT = (const float*)d_in[7];
    const float* deepT = (const float*)d_in[8];
    const float* w2    = (const float*)d_in[9];
    const float* b2    = (const float*)d_in[10];
    const float* w3    = (const float*)d_in[11];
    const float* b3    = (const float*)d_in[12];
    const float* w4    = (const float*)d_in[13];
    const float* b4    = (const float*)d_in[14];
    float* out = (float*)d_out;

    __nv_bfloat16 *X, *W2p, *W3r, *H1;
    float *H2, *wide;
    cudaGetSymbolAddress((void**)&X,    g_X);
    cudaGetSymbolAddress((void**)&W2p,  g_W2p);
    cudaGetSymbolAddress((void**)&W3r,  g_W3r);
    cudaGetSymbolAddress((void**)&H1,   g_H1);
    cudaGetSymbolAddress((void**)&H2,   g_H2);
    cudaGetSymbolAddress((void**)&wide, g_wide);

    prep_weights<<<D1 + D2, 256>>>(w2, w3, W2p, W3r);
    gather_kernel<<<BB, 128>>>(oh_i, oh_x, mi1, mx1, mi2, mx2, ctns,
                               wideT, deepT, X, wide);

    // layer 1: [B,928] x [512,928]^T -> H1[B,512] bf16
    bf16_gemm<true>
        <<<dim3(D1 / 64, BB / 128), 256>>>(X, XS, W2p, XS, b2, (void*)H1, D1, XS);

    // layer 2: [B,512] x [256,512]^T -> H2[B,256] f32
    bf16_gemm<false>
        <<<dim3(D2 / 64, BB / 128), 256>>>(H1, D1, W3r, D1, b3, (void*)H2, D2, D1);

    // layer 3 + wide + sigmoid
    final_kernel<<<BB / 8, 256>>>(H2, w4, b4, wide, out);
}

// round 7
// speedup vs baseline: 3.1289x; 1.0131x over previous
#include <cuda_runtime.h>
#include <cuda_bf16.h>
#include <math.h>
#include <stdint.h>

// ---------------- problem constants ----------------
#define BB 16384      // batch
#define FF 26         // onehot fields
#define EE 32         // embedding dim
#define LL 50         // bag length
#define D0 909
#define D1 512
#define D2 256
#define XS 928        // D0 padded (zero tail), multiple of 32

// ---------------- scratch (static device globals: allocation-free) ----------
__device__ __nv_bfloat16 g_X  [(size_t)BB * XS];   // activations bf16
__device__ __nv_bfloat16 g_W2p[(size_t)D1 * XS];   // padded w2 bf16
__device__ __nv_bfloat16 g_W3r[(size_t)D2 * D1];   // w3 bf16
__device__ __nv_bfloat16 g_H1 [(size_t)BB * D1];   // layer-1 out bf16
__device__ float         g_H2 [(size_t)BB * D2];   // layer-2 out fp32
__device__ float         g_wide[BB];

// ---------------- helpers ----------------------------------------------------
#define CP16(dst, src) \
    asm volatile("cp.async.cg.shared.global [%0], [%1], 16;\n" :: "r"(dst), "l"(src))
#define CPCOMMIT() asm volatile("cp.async.commit_group;\n" ::)
#define CPWAIT0()  asm volatile("cp.async.wait_group 0;\n" ::)
#define CPWAIT1()  asm volatile("cp.async.wait_group 1;\n" ::)

__device__ __forceinline__ void ldsm_x4(uint32_t* r, uint32_t addr) {
    asm volatile("ldmatrix.sync.aligned.m8n8.x4.shared.b16 {%0,%1,%2,%3}, [%4];"
                 : "=r"(r[0]), "=r"(r[1]), "=r"(r[2]), "=r"(r[3]) : "r"(addr));
}

__device__ __forceinline__ void mma_bf16(float* d, const uint32_t* a, const uint32_t* b) {
    asm volatile(
        "mma.sync.aligned.m16n8k16.row.col.f32.bf16.bf16.f32 "
        "{%0,%1,%2,%3}, {%4,%5,%6,%7}, {%8,%9}, {%0,%1,%2,%3};"
        : "+f"(d[0]), "+f"(d[1]), "+f"(d[2]), "+f"(d[3])
        : "r"(a[0]), "r"(a[1]), "r"(a[2]), "r"(a[3]), "r"(b[0]), "r"(b[1]));
}

// ---------------- weight prep: pad/convert w2, convert w3 -------------------
__global__ void prep_weights(const float* __restrict__ w2,
                             const float* __restrict__ w3,
                             __nv_bfloat16* __restrict__ W2p,
                             __nv_bfloat16* __restrict__ W3r)
{
    int n = blockIdx.x;
    if (n < D1) {
        for (int k = threadIdx.x; k < XS; k += blockDim.x)
            W2p[(size_t)n * XS + k] = (k < D0) ? __float2bfloat16_rn(w2[(size_t)n * D0 + k])
                                               : __float2bfloat16_rn(0.0f);
    } else {
        int m = n - D1;
        for (int k = threadIdx.x; k < D1; k += blockDim.x)
            W3r[(size_t)m * D1 + k] = __float2bfloat16_rn(w3[(size_t)m * D1 + k]);
    }
}

// ---------------- gather: build X[B,928] (bf16) + wide_sum[B] ---------------
__global__ __launch_bounds__(128) void gather_kernel(
    const int*   __restrict__ oh_i,  const float* __restrict__ oh_x,
    const int*   __restrict__ mi1,   const float* __restrict__ mx1,
    const int*   __restrict__ mi2,   const float* __restrict__ mx2,
    const float* __restrict__ ctns,
    const float* __restrict__ wideT, const float* __restrict__ deepT,
    __nv_bfloat16* __restrict__ X, float* __restrict__ wide_out)
{
    const int row  = blockIdx.x;
    const int tid  = threadIdx.x;
    const int warp = tid >> 5;
    const int lane = tid & 31;
    __nv_bfloat16* xr = X + (size_t)row * XS;

    for (int f = warp; f < FF; f += 4) {
        int   idx = oh_i[row * FF + f];
        float w   = oh_x[row * FF + f];
        xr[f * EE + lane] = __float2bfloat16_rn(deepT[(size_t)idx * EE + lane] * w);
    }

    {
        const int*   mi = (warp < 2) ? mi1 : mi2;
        const float* mx = (warp < 2) ? mx1 : mx2;
        const int half  = warp & 1;
        float acc = 0.0f;
        for (int j = half; j < LL; j += 2) {
            int   idx = mi[row * LL + j];
            float w   = mx[row * LL + j];
            acc += deepT[(size_t)idx * EE + lane] * w;
        }
        __shared__ float sb[4][EE];
        sb[warp][lane] = acc;
        __syncthreads();
        if      (warp == 0) xr[FF * EE      + lane] = __float2bfloat16_rn(sb[0][lane] + sb[1][lane]);
        else if (warp == 1) xr[FF * EE + EE + lane] = __float2bfloat16_rn(sb[2][lane] + sb[3][lane]);
        else if (warp == 2) { if (lane < 13) xr[FF * EE + 2 * EE + lane] = __float2bfloat16_rn(ctns[row * 13 + lane]); }
        else                { if (lane < XS - D0) xr[D0 + lane] = __float2bfloat16_rn(0.0f); }
    }

    float wv = 0.0f;
    if (tid < FF) {
        wv = wideT[oh_i[row * FF + tid]] * oh_x[row * FF + tid];
    } else if (tid < FF + LL) {
        int j = tid - FF;
        wv = wideT[mi1[row * LL + j]] * mx1[row * LL + j];
    } else if (tid < FF + 2 * LL) {
        int j = tid - FF - LL;
        wv = wideT[mi2[row * LL + j]] * mx2[row * LL + j];
    }
    #pragma unroll
    for (int o = 16; o; o >>= 1) wv += __shfl_xor_sync(0xFFFFFFFFu, wv, o);
    __shared__ float swide[4];
    if (lane == 0) swide[warp] = wv;
    __syncthreads();
    if (tid == 0)
        wide_out[row] = swide[0] + swide[1] + swide[2] + swide[3];
}

// ---------------- bf16 mma.sync GEMM: C = A(M,K) * B(N,K)^T -----------------
// block 128x128, BK=32, 3-stage cp.async pipeline, DYNAMIC smem (60 KB).
// 8 warps as 2(M) x 4(N); warp tile 64x32 -> 32 MMAs per 16-k slab pair.
template <bool OUT_BF16>
__global__ void __launch_bounds__(256) bf16_gemm(
    const __nv_bfloat16* __restrict__ A, int lda,
    const __nv_bfloat16* __restrict__ Bm, int ldb,
    const float* __restrict__ bias,
    void* __restrict__ Cv, int ldc, int K)
{
    constexpr int BM = 128, BN = 128, BK = 32, LDA = BK + 8;   // 40 bf16 = 80 B stride
    constexpr int ST = 3;
    constexpr int A_ELEMS = BM * LDA;          // per stage
    constexpr int B_ELEMS = BN * LDA;

    extern __shared__ __align__(16) __nv_bfloat16 smem[];
    __nv_bfloat16* Asm = smem;                      // [ST][BM][LDA]
    __nv_bfloat16* Bsm = smem + ST * A_ELEMS;       // [ST][BN][LDA]

    const int tid  = threadIdx.x;
    const int warp = tid >> 5;
    const int lane = tid & 31;
    const int wm = (warp & 1) * 64;        // 2 warps in M, tile 64
    const int wn = (warp >> 1) * 32;       // 4 warps in N, tile 32
    const int r  = lane >> 2;              // 0..7
    const int c  = lane & 3;               // 0..3

    const int bm = blockIdx.y * BM;
    const int bn = blockIdx.x * BN;

    // cp.async loader coords: 2 chunks per thread per tile-half
    const int lrow = tid >> 2;             // 0..63
    const int lcol = (tid & 3) * 8;        // 0,8,16,24
    const __nv_bfloat16* gA0 = A  + (size_t)(bm + lrow)      * lda + lcol;
    const __nv_bfloat16* gA1 = A  + (size_t)(bm + lrow + 64) * lda + lcol;
    const __nv_bfloat16* gB0 = Bm + (size_t)(bn + lrow)      * ldb + lcol;
    const __nv_bfloat16* gB1 = Bm + (size_t)(bn + lrow + 64) * ldb + lcol;

    uint32_t sA0[ST], sA1[ST], sB0[ST], sB1[ST];
    #pragma unroll
    for (int s = 0; s < ST; s++) {
        sA0[s] = (uint32_t)__cvta_generic_to_shared(&Asm[s * A_ELEMS + lrow * LDA + lcol]);
        sA1[s] = (uint32_t)__cvta_generic_to_shared(&Asm[s * A_ELEMS + (lrow + 64) * LDA + lcol]);
        sB0[s] = (uint32_t)__cvta_generic_to_shared(&Bsm[s * B_ELEMS + lrow * LDA + lcol]);
        sB1[s] = (uint32_t)__cvta_generic_to_shared(&Bsm[s * B_ELEMS + (lrow + 64) * LDA + lcol]);
    }

    // ldmatrix lane address mapping
    const int rowA_l = lane & 15;
    const int colA_l = (lane >> 4) << 3;
    const int rowB_l = (lane & 7) + ((lane & 16) >> 1);
    const int colB_l = lane & 8;
    uint32_t aBase[ST], bBase[ST];
    #pragma unroll
    for (int s = 0; s < ST; s++) {
        aBase[s] = (uint32_t)__cvta_generic_to_shared(
            &Asm[s * A_ELEMS + (wm + rowA_l) * LDA + colA_l]);
        bBase[s] = (uint32_t)__cvta_generic_to_shared(
            &Bsm[s * B_ELEMS + (wn + rowB_l) * LDA + colB_l]);
    }

    float acc[4][4][4];
    #pragma unroll
    for (int i = 0; i < 4; i++)
        #pragma unroll
        for (int j = 0; j < 4; j++)
            #pragma unroll
            for (int q = 0; q < 4; q++) acc[i][j][q] = 0.0f;

    const int T = K / BK;

    // prologue: stages 0,1 in flight as separate groups
    #pragma unroll
    for (int s = 0; s < 2; s++) {
        int k0 = s * BK;
        CP16(sA0[s], gA0 + k0);
        CP16(sA1[s], gA1 + k0);
        CP16(sB0[s], gB0 + k0);
        CP16(sB1[s], gB1 + k0);
        CPCOMMIT();
    }

    int st = 0;
    for (int t = 0; t < T; t++) {
        if (t + 1 < T) CPWAIT1(); else CPWAIT0();
        __syncthreads();      // stage t visible; all warps done with stage (t+2)%ST buffer

        if (t + 2 < T) {
            int ns = st + 2; if (ns >= ST) ns -= ST;
            int k0 = (t + 2) * BK;
            CP16(sA0[ns], gA0 + k0);
            CP16(sA1[ns], gA1 + k0);
            CP16(sB0[ns], gB0 + k0);
            CP16(sB1[ns], gB1 + k0);
            CPCOMMIT();
        }

        #pragma unroll
        for (int kk = 0; kk < BK; kk += 16) {
            uint32_t af[4][4], bq[2][4];
            #pragma unroll
            for (int i = 0; i < 4; i++)
                ldsm_x4(af[i], aBase[st] + (uint32_t)((16 * i * LDA + kk) * 2));
            #pragma unroll
            for (int j16 = 0; j16 < 2; j16++)
                ldsm_x4(bq[j16], bBase[st] + (uint32_t)((16 * j16 * LDA + kk) * 2));
            #pragma unroll
            for (int i = 0; i < 4; i++)
                #pragma unroll
                for (int j = 0; j < 4; j++)
                    mma_bf16(acc[i][j], af[i], &bq[j >> 1][(j & 1) * 2]);
        }
        if (++st == ST) st = 0;
    }

    // epilogue: bias + leaky
    #pragma unroll
    for (int i = 0; i < 4; i++) {
        #pragma unroll
        for (int j = 0; j < 4; j++) {
            const int n0 = bn + wn + 8 * j + c * 2;
            const float bi0 = __ldg(&bias[n0]);
            const float bi1 = __ldg(&bias[n0 + 1]);
            #pragma unroll
            for (int h = 0; h < 2; h++) {
                const int m = bm + wm + 16 * i + r + 8 * h;
                float v0 = acc[i][j][2 * h + 0] + bi0;
                float v1 = acc[i][j][2 * h + 1] + bi1;
                v0 = (v0 >= 0.0f) ? v0 : 0.01f * v0;
                v1 = (v1 >= 0.0f) ? v1 : 0.01f * v1;
                if (OUT_BF16) {
                    __nv_bfloat162 o = make_bfloat162(__float2bfloat16_rn(v0),
                                                      __float2bfloat16_rn(v1));
                    *reinterpret_cast<__nv_bfloat162*>(
                        &((__nv_bfloat16*)Cv)[(size_t)m * ldc + n0]) = o;
                } else {
                    float2 o = make_float2(v0, v1);
                    *reinterpret_cast<float2*>(&((float*)Cv)[(size_t)m * ldc + n0]) = o;
                }
            }
        }
    }
}

// ---------------- final: out = sigmoid(H2 . w4 + b4 + 32*wide) --------------
__global__ __launch_bounds__(256) void final_kernel(
    const float* __restrict__ H2, const float* __restrict__ w4,
    const float* __restrict__ b4, const float* __restrict__ wide,
    float* __restrict__ out)
{
    __shared__ float sw4[D2];
    int tid = threadIdx.x;
    sw4[tid] = w4[tid];
    __syncthreads();

    int warp = tid >> 5, lane = tid & 31;
    int row  = blockIdx.x * 8 + warp;
    const float* h = H2 + (size_t)row * D2;
    float acc = 0.0f;
    #pragma unroll
    for (int i = 0; i < D2 / 32; i++)
        acc += h[lane + i * 32] * sw4[lane + i * 32];
    #pragma unroll
    for (int o = 16; o; o >>= 1) acc += __shfl_xor_sync(0xFFFFFFFFu, acc, o);
    if (lane == 0) {
        float z = acc + b4[0] + (float)EE * wide[row];
        out[row] = 1.0f / (1.0f + expf(-z));
    }
}

// ---------------- launch ----------------------------------------------------
extern "C" void kernel_launch(void* const* d_in, const int* in_sizes, int n_in,
                              void* d_out, int out_size)
{
    const int*   oh_i  = (const int*)  d_in[0];
    const float* oh_x  = (const float*)d_in[1];
    const int*   mi1   = (const int*)  d_in[2];
    const float* mx1   = (const float*)d_in[3];
    const int*   mi2   = (const int*)  d_in[4];
    const float* mx2   = (const float*)d_in[5];
    const float* ctns  = (const float*)d_in[6];
    const float* wideT = (const float*)d_in[7];
    const float* deepT = (const float*)d_in[8];
    const float* w2    = (const float*)d_in[9];
    const float* b2    = (const float*)d_in[10];
    const float* w3    = (const float*)d_in[11];
    const float* b3    = (const float*)d_in[12];
    const float* w4    = (const float*)d_in[13];
    const float* b4    = (const float*)d_in[14];
    float* out = (float*)d_out;

    __nv_bfloat16 *X, *W2p, *W3r, *H1;
    float *H2, *wide;
    cudaGetSymbolAddress((void**)&X,    g_X);
    cudaGetSymbolAddress((void**)&W2p,  g_W2p);
    cudaGetSymbolAddress((void**)&W3r,  g_W3r);
    cudaGetSymbolAddress((void**)&H1,   g_H1);
    cudaGetSymbolAddress((void**)&H2,   g_H2);
    cudaGetSymbolAddress((void**)&wide, g_wide);

    // dynamic smem: 3 stages * (128+128) rows * 40 bf16 = 61440 bytes
    const int SMEM = 3 * (128 + 128) * 40 * 2;
    static int attr_done = 0;
    if (!attr_done) {
        cudaFuncSetAttribute(bf16_gemm<true>,
                             cudaFuncAttributeMaxDynamicSharedMemorySize, SMEM);
        cudaFuncSetAttribute(bf16_gemm<false>,
                             cudaFuncAttributeMaxDynamicSharedMemorySize, SMEM);
        attr_done = 1;
    }

    prep_weights<<<D1 + D2, 256>>>(w2, w3, W2p, W3r);
    gather_kernel<<<BB, 128>>>(oh_i, oh_x, mi1, mx1, mi2, mx2, ctns,
                               wideT, deepT, X, wide);

    // layer 1: [B,928] x [512,928]^T -> H1[B,512] bf16
    bf16_gemm<true>
        <<<dim3(D1 / 128, BB / 128), 256, SMEM>>>(X, XS, W2p, XS, b2, (void*)H1, D1, XS);

    // layer 2: [B,512] x [256,512]^T -> H2[B,256] f32
    bf16_gemm<false>
        <<<dim3(D2 / 128, BB / 128), 256, SMEM>>>(H1, D1, W3r, D1, b3, (void*)H2, D2, D1);

    // layer 3 + wide + sigmoid
    final_kernel<<<BB / 8, 256>>>(H2, w4, b4, wide, out);
}

// round 8
// speedup vs baseline: 3.3446x; 1.0690x over previous
#include <cuda_runtime.h>
#include <cuda_bf16.h>
#include <math.h>
#include <stdint.h>

// ---------------- problem constants ----------------
#define BB 16384      // batch
#define FF 26         // onehot fields
#define EE 32         // embedding dim
#define LL 50         // bag length
#define D0 909
#define D1 512
#define D2 256
#define XS 960        // D0 padded (zero tail), multiple of 64

// ---------------- scratch (static device globals: allocation-free) ----------
__device__ __nv_bfloat16 g_X  [(size_t)BB * XS];   // activations bf16
__device__ __nv_bfloat16 g_W2p[(size_t)D1 * XS];   // padded w2 bf16
__device__ __nv_bfloat16 g_W3r[(size_t)D2 * D1];   // w3 bf16
__device__ __nv_bfloat16 g_H1 [(size_t)BB * D1];   // layer-1 out bf16
__device__ float         g_H2 [(size_t)BB * D2];   // layer-2 out fp32
__device__ float         g_wide[BB];

// ---------------- helpers ----------------------------------------------------
#define CP16(dst, src) \
    asm volatile("cp.async.cg.shared.global [%0], [%1], 16;\n" :: "r"(dst), "l"(src))
#define CPCOMMIT() asm volatile("cp.async.commit_group;\n" ::)
#define CPWAIT0()  asm volatile("cp.async.wait_group 0;\n" ::)
#define CPWAIT1()  asm volatile("cp.async.wait_group 1;\n" ::)

__device__ __forceinline__ void ldsm_x4(uint32_t* r, uint32_t addr) {
    asm volatile("ldmatrix.sync.aligned.m8n8.x4.shared.b16 {%0,%1,%2,%3}, [%4];"
                 : "=r"(r[0]), "=r"(r[1]), "=r"(r[2]), "=r"(r[3]) : "r"(addr));
}

__device__ __forceinline__ void mma_bf16(float* d, const uint32_t* a, const uint32_t* b) {
    asm volatile(
        "mma.sync.aligned.m16n8k16.row.col.f32.bf16.bf16.f32 "
        "{%0,%1,%2,%3}, {%4,%5,%6,%7}, {%8,%9}, {%0,%1,%2,%3};"
        : "+f"(d[0]), "+f"(d[1]), "+f"(d[2]), "+f"(d[3])
        : "r"(a[0]), "r"(a[1]), "r"(a[2]), "r"(a[3]), "r"(b[0]), "r"(b[1]));
}

// ---------------- gather + weight prep (fused launch) ------------------------
// blocks [0, BB): gather one batch row.  blocks [BB, BB+D1+D2): weight prep.
__global__ __launch_bounds__(128) void gather_kernel(
    const int*   __restrict__ oh_i,  const float* __restrict__ oh_x,
    const int*   __restrict__ mi1,   const float* __restrict__ mx1,
    const int*   __restrict__ mi2,   const float* __restrict__ mx2,
    const float* __restrict__ ctns,
    const float* __restrict__ wideT, const float* __restrict__ deepT,
    const float* __restrict__ w2,    const float* __restrict__ w3,
    __nv_bfloat16* __restrict__ X,   float* __restrict__ wide_out,
    __nv_bfloat16* __restrict__ W2p, __nv_bfloat16* __restrict__ W3r)
{
    const int tid  = threadIdx.x;

    if (blockIdx.x >= BB) {
        int n = blockIdx.x - BB;
        if (n < D1) {
            for (int k = tid; k < XS; k += 128)
                W2p[(size_t)n * XS + k] = (k < D0) ? __float2bfloat16_rn(w2[(size_t)n * D0 + k])
                                                   : __float2bfloat16_rn(0.0f);
        } else {
            int m = n - D1;
            for (int k = tid; k < D1; k += 128)
                W3r[(size_t)m * D1 + k] = __float2bfloat16_rn(w3[(size_t)m * D1 + k]);
        }
        return;
    }

    const int row  = blockIdx.x;
    const int warp = tid >> 5;
    const int lane = tid & 31;
    __nv_bfloat16* xr = X + (size_t)row * XS;

    for (int f = warp; f < FF; f += 4) {
        int   idx = oh_i[row * FF + f];
        float w   = oh_x[row * FF + f];
        xr[f * EE + lane] = __float2bfloat16_rn(deepT[(size_t)idx * EE + lane] * w);
    }

    {
        const int*   mi = (warp < 2) ? mi1 : mi2;
        const float* mx = (warp < 2) ? mx1 : mx2;
        const int half  = warp & 1;
        float acc = 0.0f;
        for (int j = half; j < LL; j += 2) {
            int   idx = mi[row * LL + j];
            float w   = mx[row * LL + j];
            acc += deepT[(size_t)idx * EE + lane] * w;
        }
        __shared__ float sb[4][EE];
        sb[warp][lane] = acc;
        __syncthreads();
        if      (warp == 0) xr[FF * EE      + lane] = __float2bfloat16_rn(sb[0][lane] + sb[1][lane]);
        else if (warp == 1) xr[FF * EE + EE + lane] = __float2bfloat16_rn(sb[2][lane] + sb[3][lane]);
        else if (warp == 2) { if (lane < 13) xr[FF * EE + 2 * EE + lane] = __float2bfloat16_rn(ctns[row * 13 + lane]); }
    }
    if (tid < XS - D0) xr[D0 + tid] = __float2bfloat16_rn(0.0f);   // zero pad tail

    float wv = 0.0f;
    if (tid < FF) {
        wv = wideT[oh_i[row * FF + tid]] * oh_x[row * FF + tid];
    } else if (tid < FF + LL) {
        int j = tid - FF;
        wv = wideT[mi1[row * LL + j]] * mx1[row * LL + j];
    } else if (tid < FF + 2 * LL) {
        int j = tid - FF - LL;
        wv = wideT[mi2[row * LL + j]] * mx2[row * LL + j];
    }
    #pragma unroll
    for (int o = 16; o; o >>= 1) wv += __shfl_xor_sync(0xFFFFFFFFu, wv, o);
    __shared__ float swide[4];
    if (lane == 0) swide[warp] = wv;
    __syncthreads();
    if (tid == 0)
        wide_out[row] = swide[0] + swide[1] + swide[2] + swide[3];
}

// ---------------- bf16 mma.sync GEMM: C = A(M,K) * B(N,K)^T -----------------
// block 128x128, BK=64, 3-stage cp.async pipeline, dynamic smem (108 KB).
// 8 warps as 2(M) x 4(N); warp 64x32 -> 64 MMAs + 24 LDSM between barriers.
template <bool OUT_BF16>
__global__ void __launch_bounds__(256, 2) bf16_gemm(
    const __nv_bfloat16* __restrict__ A, int lda,
    const __nv_bfloat16* __restrict__ Bm, int ldb,
    const float* __restrict__ bias,
    void* __restrict__ Cv, int ldc, int K)
{
    constexpr int BM = 128, BN = 128, BK = 64, LDA = BK + 8;   // 72 bf16 = 144 B stride
    constexpr int ST = 3;
    constexpr int A_ELEMS = BM * LDA;
    constexpr int B_ELEMS = BN * LDA;

    extern __shared__ __align__(16) __nv_bfloat16 smem[];
    __nv_bfloat16* Asm = smem;                      // [ST][BM][LDA]
    __nv_bfloat16* Bsm = smem + ST * A_ELEMS;       // [ST][BN][LDA]

    const int tid  = threadIdx.x;
    const int warp = tid >> 5;
    const int lane = tid & 31;
    const int wm = (warp & 1) * 64;        // 2 warps in M
    const int wn = (warp >> 1) * 32;       // 4 warps in N
    const int r  = lane >> 2;
    const int c  = lane & 3;

    const int bm = blockIdx.y * BM;
    const int bn = blockIdx.x * BN;

    // cp.async loader coords: 64 cols = 8 chunks/row; 256 thr cover 32 rows/iter
    const int lrow = tid >> 3;             // 0..31
    const int lcol = (tid & 7) * 8;        // 0..56
    const __nv_bfloat16* gA = A  + (size_t)(bm + lrow) * lda + lcol;
    const __nv_bfloat16* gB = Bm + (size_t)(bn + lrow) * ldb + lcol;

    uint32_t sAbase[ST], sBbase[ST];
    #pragma unroll
    for (int s = 0; s < ST; s++) {
        sAbase[s] = (uint32_t)__cvta_generic_to_shared(&Asm[s * A_ELEMS + lrow * LDA + lcol]);
        sBbase[s] = (uint32_t)__cvta_generic_to_shared(&Bsm[s * B_ELEMS + lrow * LDA + lcol]);
    }

    // ldmatrix lane address mapping
    const int rowA_l = lane & 15;
    const int colA_l = (lane >> 4) << 3;
    const int rowB_l = (lane & 7) + ((lane & 16) >> 1);
    const int colB_l = lane & 8;
    uint32_t aBase[ST], bBase[ST];
    #pragma unroll
    for (int s = 0; s < ST; s++) {
        aBase[s] = (uint32_t)__cvta_generic_to_shared(
            &Asm[s * A_ELEMS + (wm + rowA_l) * LDA + colA_l]);
        bBase[s] = (uint32_t)__cvta_generic_to_shared(
            &Bsm[s * B_ELEMS + (wn + rowB_l) * LDA + colB_l]);
    }

    float acc[4][4][4];
    #pragma unroll
    for (int i = 0; i < 4; i++)
        #pragma unroll
        for (int j = 0; j < 4; j++)
            #pragma unroll
            for (int q = 0; q < 4; q++) acc[i][j][q] = 0.0f;

    const int T = K / BK;

    // tile loader: 4 row-groups of 32 for A and B each (8 CP16/thread)
    auto load_stage = [&](int s, int k0) {
        #pragma unroll
        for (int g = 0; g < 4; g++)
            CP16(sAbase[s] + (uint32_t)(g * 32 * LDA * 2),
                 gA + (size_t)(g * 32) * lda + k0);
        #pragma unroll
        for (int g = 0; g < 4; g++)
            CP16(sBbase[s] + (uint32_t)(g * 32 * LDA * 2),
                 gB + (size_t)(g * 32) * ldb + k0);
        CPCOMMIT();
    };

    // prologue: stages 0,1
    load_stage(0, 0);
    load_stage(1, BK);

    int st = 0;
    for (int t = 0; t < T; t++) {
        if (t + 1 < T) CPWAIT1(); else CPWAIT0();
        __syncthreads();

        if (t + 2 < T) {
            int ns = st + 2; if (ns >= ST) ns -= ST;
            load_stage(ns, (t + 2) * BK);
        }

        #pragma unroll
        for (int kk = 0; kk < BK; kk += 16) {
            uint32_t af[4][4], bq[2][4];
            #pragma unroll
            for (int i = 0; i < 4; i++)
                ldsm_x4(af[i], aBase[st] + (uint32_t)((16 * i * LDA + kk) * 2));
            #pragma unroll
            for (int j16 = 0; j16 < 2; j16++)
                ldsm_x4(bq[j16], bBase[st] + (uint32_t)((16 * j16 * LDA + kk) * 2));
            #pragma unroll
            for (int i = 0; i < 4; i++)
                #pragma unroll
                for (int j = 0; j < 4; j++)
                    mma_bf16(acc[i][j], af[i], &bq[j >> 1][(j & 1) * 2]);
        }
        if (++st == ST) st = 0;
    }

    // epilogue: bias + leaky
    #pragma unroll
    for (int i = 0; i < 4; i++) {
        #pragma unroll
        for (int j = 0; j < 4; j++) {
            const int n0 = bn + wn + 8 * j + c * 2;
            const float bi0 = __ldg(&bias[n0]);
            const float bi1 = __ldg(&bias[n0 + 1]);
            #pragma unroll
            for (int h = 0; h < 2; h++) {
                const int m = bm + wm + 16 * i + r + 8 * h;
                float v0 = acc[i][j][2 * h + 0] + bi0;
                float v1 = acc[i][j][2 * h + 1] + bi1;
                v0 = (v0 >= 0.0f) ? v0 : 0.01f * v0;
                v1 = (v1 >= 0.0f) ? v1 : 0.01f * v1;
                if (OUT_BF16) {
                    __nv_bfloat162 o = make_bfloat162(__float2bfloat16_rn(v0),
                                                      __float2bfloat16_rn(v1));
                    *reinterpret_cast<__nv_bfloat162*>(
                        &((__nv_bfloat16*)Cv)[(size_t)m * ldc + n0]) = o;
                } else {
                    float2 o = make_float2(v0, v1);
                    *reinterpret_cast<float2*>(&((float*)Cv)[(size_t)m * ldc + n0]) = o;
                }
            }
        }
    }
}

// ---------------- final: out = sigmoid(H2 . w4 + b4 + 32*wide) --------------
__global__ __launch_bounds__(256) void final_kernel(
    const float* __restrict__ H2, const float* __restrict__ w4,
    const float* __restrict__ b4, const float* __restrict__ wide,
    float* __restrict__ out)
{
    __shared__ float sw4[D2];
    int tid = threadIdx.x;
    sw4[tid] = w4[tid];
    __syncthreads();

    int warp = tid >> 5, lane = tid & 31;
    int row  = blockIdx.x * 8 + warp;
    const float* h = H2 + (size_t)row * D2;
    float acc = 0.0f;
    #pragma unroll
    for (int i = 0; i < D2 / 32; i++)
        acc += h[lane + i * 32] * sw4[lane + i * 32];
    #pragma unroll
    for (int o = 16; o; o >>= 1) acc += __shfl_xor_sync(0xFFFFFFFFu, acc, o);
    if (lane == 0) {
        float z = acc + b4[0] + (float)EE * wide[row];
        out[row] = 1.0f / (1.0f + expf(-z));
    }
}

// ---------------- launch ----------------------------------------------------
extern "C" void kernel_launch(void* const* d_in, const int* in_sizes, int n_in,
                              void* d_out, int out_size)
{
    const int*   oh_i  = (const int*)  d_in[0];
    const float* oh_x  = (const float*)d_in[1];
    const int*   mi1   = (const int*)  d_in[2];
    const float* mx1   = (const float*)d_in[3];
    const int*   mi2   = (const int*)  d_in[4];
    const float* mx2   = (const float*)d_in[5];
    const float* ctns  = (const float*)d_in[6];
    const float* wideT = (const float*)d_in[7];
    const float* deepT = (const float*)d_in[8];
    const float* w2    = (const float*)d_in[9];
    const float* b2    = (const float*)d_in[10];
    const float* w3    = (const float*)d_in[11];
    const float* b3    = (const float*)d_in[12];
    const float* w4    = (const float*)d_in[13];
    const float* b4    = (const float*)d_in[14];
    float* out = (float*)d_out;

    __nv_bfloat16 *X, *W2p, *W3r, *H1;
    float *H2, *wide;
    cudaGetSymbolAddress((void**)&X,    g_X);
    cudaGetSymbolAddress((void**)&W2p,  g_W2p);
    cudaGetSymbolAddress((void**)&W3r,  g_W3r);
    cudaGetSymbolAddress((void**)&H1,   g_H1);
    cudaGetSymbolAddress((void**)&H2,   g_H2);
    cudaGetSymbolAddress((void**)&wide, g_wide);

    // dynamic smem: 3 stages * (128+128) rows * 72 bf16 = 110592 bytes
    const int SMEM = 3 * (128 + 128) * 72 * 2;
    static int attr_done = 0;
    if (!attr_done) {
        cudaFuncSetAttribute(bf16_gemm<true>,
                             cudaFuncAttributeMaxDynamicSharedMemorySize, SMEM);
        cudaFuncSetAttribute(bf16_gemm<false>,
                             cudaFuncAttributeMaxDynamicSharedMemorySize, SMEM);
        attr_done = 1;
    }

    // fused gather + weight prep
    gather_kernel<<<BB + D1 + D2, 128>>>(oh_i, oh_x, mi1, mx1, mi2, mx2, ctns,
                                         wideT, deepT, w2, w3,
                                         X, wide, W2p, W3r);

    // layer 1: [B,960] x [512,960]^T -> H1[B,512] bf16
    bf16_gemm<true>
        <<<dim3(D1 / 128, BB / 128), 256, SMEM>>>(X, XS, W2p, XS, b2, (void*)H1, D1, XS);

    // layer 2: [B,512] x [256,512]^T -> H2[B,256] f32
    bf16_gemm<false>
        <<<dim3(D2 / 128, BB / 128), 256, SMEM>>>(H1, D1, W3r, D1, b3, (void*)H2, D2, D1);

    // layer 3 + wide + sigmoid
    final_kernel<<<BB / 8, 256>>>(H2, w4, b4, wide, out);
}

// round 9
// speedup vs baseline: 3.4744x; 1.0388x over previous
#include <cuda_runtime.h>
#include <cuda_bf16.h>
#include <math.h>
#include <stdint.h>

// ---------------- problem constants ----------------
#define BB 16384      // batch
#define FF 26         // onehot fields
#define EE 32         // embedding dim
#define LL 50         // bag length
#define D0 909
#define D1 512
#define D2 256
#define XS 960        // D0 padded (zero tail), multiple of 64

// ---------------- scratch (static device globals: allocation-free) ----------
__device__ __nv_bfloat16 g_X  [(size_t)BB * XS];   // activations bf16
__device__ __nv_bfloat16 g_W2p[(size_t)D1 * XS];   // padded w2 bf16
__device__ __nv_bfloat16 g_W3r[(size_t)D2 * D1];   // w3 bf16
__device__ __nv_bfloat16 g_H1 [(size_t)BB * D1];   // layer-1 out bf16
__device__ float         g_zp [(size_t)8 * BB];    // fused layer-3 partials
__device__ float         g_wide[BB];

// ---------------- helpers ----------------------------------------------------
#define CP16(dst, src) \
    asm volatile("cp.async.cg.shared.global [%0], [%1], 16;\n" :: "r"(dst), "l"(src))
#define CPCOMMIT() asm volatile("cp.async.commit_group;\n" ::)
#define CPWAIT0()  asm volatile("cp.async.wait_group 0;\n" ::)
#define CPWAIT1()  asm volatile("cp.async.wait_group 1;\n" ::)

__device__ __forceinline__ void ldsm_x4(uint32_t* r, uint32_t addr) {
    asm volatile("ldmatrix.sync.aligned.m8n8.x4.shared.b16 {%0,%1,%2,%3}, [%4];"
                 : "=r"(r[0]), "=r"(r[1]), "=r"(r[2]), "=r"(r[3]) : "r"(addr));
}

__device__ __forceinline__ void mma_bf16(float* d, const uint32_t* a, const uint32_t* b) {
    asm volatile(
        "mma.sync.aligned.m16n8k16.row.col.f32.bf16.bf16.f32 "
        "{%0,%1,%2,%3}, {%4,%5,%6,%7}, {%8,%9}, {%0,%1,%2,%3};"
        : "+f"(d[0]), "+f"(d[1]), "+f"(d[2]), "+f"(d[3])
        : "r"(a[0]), "r"(a[1]), "r"(a[2]), "r"(a[3]), "r"(b[0]), "r"(b[1]));
}

// ---------------- gather + weight prep (fused launch) ------------------------
__global__ __launch_bounds__(128) void gather_kernel(
    const int*   __restrict__ oh_i,  const float* __restrict__ oh_x,
    const int*   __restrict__ mi1,   const float* __restrict__ mx1,
    const int*   __restrict__ mi2,   const float* __restrict__ mx2,
    const float* __restrict__ ctns,
    const float* __restrict__ wideT, const float* __restrict__ deepT,
    const float* __restrict__ w2,    const float* __restrict__ w3,
    __nv_bfloat16* __restrict__ X,   float* __restrict__ wide_out,
    __nv_bfloat16* __restrict__ W2p, __nv_bfloat16* __restrict__ W3r)
{
    const int tid  = threadIdx.x;

    if (blockIdx.x >= BB) {
        int n = blockIdx.x - BB;
        if (n < D1) {
            for (int k = tid; k < XS; k += 128)
                W2p[(size_t)n * XS + k] = (k < D0) ? __float2bfloat16_rn(w2[(size_t)n * D0 + k])
                                                   : __float2bfloat16_rn(0.0f);
        } else {
            int m = n - D1;
            for (int k = tid; k < D1; k += 128)
                W3r[(size_t)m * D1 + k] = __float2bfloat16_rn(w3[(size_t)m * D1 + k]);
        }
        return;
    }

    const int row  = blockIdx.x;
    const int warp = tid >> 5;
    const int lane = tid & 31;
    __nv_bfloat16* xr = X + (size_t)row * XS;

    for (int f = warp; f < FF; f += 4) {
        int   idx = oh_i[row * FF + f];
        float w   = oh_x[row * FF + f];
        xr[f * EE + lane] = __float2bfloat16_rn(deepT[(size_t)idx * EE + lane] * w);
    }

    {
        const int*   mi = (warp < 2) ? mi1 : mi2;
        const float* mx = (warp < 2) ? mx1 : mx2;
        const int half  = warp & 1;
        float acc = 0.0f;
        for (int j = half; j < LL; j += 2) {
            int   idx = mi[row * LL + j];
            float w   = mx[row * LL + j];
            acc += deepT[(size_t)idx * EE + lane] * w;
        }
        __shared__ float sb[4][EE];
        sb[warp][lane] = acc;
        __syncthreads();
        if      (warp == 0) xr[FF * EE      + lane] = __float2bfloat16_rn(sb[0][lane] + sb[1][lane]);
        else if (warp == 1) xr[FF * EE + EE + lane] = __float2bfloat16_rn(sb[2][lane] + sb[3][lane]);
        else if (warp == 2) { if (lane < 13) xr[FF * EE + 2 * EE + lane] = __float2bfloat16_rn(ctns[row * 13 + lane]); }
    }
    if (tid < XS - D0) xr[D0 + tid] = __float2bfloat16_rn(0.0f);   // zero pad tail

    float wv = 0.0f;
    if (tid < FF) {
        wv = wideT[oh_i[row * FF + tid]] * oh_x[row * FF + tid];
    } else if (tid < FF + LL) {
        int j = tid - FF;
        wv = wideT[mi1[row * LL + j]] * mx1[row * LL + j];
    } else if (tid < FF + 2 * LL) {
        int j = tid - FF - LL;
        wv = wideT[mi2[row * LL + j]] * mx2[row * LL + j];
    }
    #pragma unroll
    for (int o = 16; o; o >>= 1) wv += __shfl_xor_sync(0xFFFFFFFFu, wv, o);
    __shared__ float swide[4];
    if (lane == 0) swide[warp] = wv;
    __syncthreads();
    if (tid == 0)
        wide_out[row] = swide[0] + swide[1] + swide[2] + swide[3];
}

// ---------------- bf16 mma.sync GEMM: C = A(M,K) * B(N,K)^T -----------------
// block 128x128, BK=64, 3-stage cp.async pipeline, dynamic smem (108 KB).
// 8 warps as 2(M) x 4(N), warp tile 64x32; register double-buffered fragments.
// MODE 0: bf16 C store (bias+leaky).  MODE 1: fused layer-3 — bias+leaky,
// dot with w4, quad-reduce, write per-warp partial to zp[p][m] (no C store).
template <int MODE>
__global__ void __launch_bounds__(256, 2) bf16_gemm(
    const __nv_bfloat16* __restrict__ A, int lda,
    const __nv_bfloat16* __restrict__ Bm, int ldb,
    const float* __restrict__ bias,
    void* __restrict__ Cv, int ldc, int K,
    const float* __restrict__ w4, float* __restrict__ zp)
{
    constexpr int BM = 128, BN = 128, BK = 64, LDA = BK + 8;   // 72 bf16 = 144 B
    constexpr int ST = 3;
    constexpr int A_ELEMS = BM * LDA;
    constexpr int B_ELEMS = BN * LDA;

    extern __shared__ __align__(16) __nv_bfloat16 smem[];
    __nv_bfloat16* Asm = smem;
    __nv_bfloat16* Bsm = smem + ST * A_ELEMS;

    const int tid  = threadIdx.x;
    const int warp = tid >> 5;
    const int lane = tid & 31;
    const int wm = (warp & 1) * 64;        // 2 warps in M
    const int wn = (warp >> 1) * 32;       // 4 warps in N
    const int r  = lane >> 2;
    const int c  = lane & 3;

    const int bm = blockIdx.y * BM;
    const int bn = blockIdx.x * BN;

    const int lrow = tid >> 3;             // 0..31
    const int lcol = (tid & 7) * 8;        // 0..56
    const __nv_bfloat16* gA = A  + (size_t)(bm + lrow) * lda + lcol;
    const __nv_bfloat16* gB = Bm + (size_t)(bn + lrow) * ldb + lcol;

    uint32_t sAbase[ST], sBbase[ST];
    #pragma unroll
    for (int s = 0; s < ST; s++) {
        sAbase[s] = (uint32_t)__cvta_generic_to_shared(&Asm[s * A_ELEMS + lrow * LDA + lcol]);
        sBbase[s] = (uint32_t)__cvta_generic_to_shared(&Bsm[s * B_ELEMS + lrow * LDA + lcol]);
    }

    const int rowA_l = lane & 15;
    const int colA_l = (lane >> 4) << 3;
    const int rowB_l = (lane & 7) + ((lane & 16) >> 1);
    const int colB_l = lane & 8;
    uint32_t aBase[ST], bBase[ST];
    #pragma unroll
    for (int s = 0; s < ST; s++) {
        aBase[s] = (uint32_t)__cvta_generic_to_shared(
            &Asm[s * A_ELEMS + (wm + rowA_l) * LDA + colA_l]);
        bBase[s] = (uint32_t)__cvta_generic_to_shared(
            &Bsm[s * B_ELEMS + (wn + rowB_l) * LDA + colB_l]);
    }

    float acc[4][4][4];
    #pragma unroll
    for (int i = 0; i < 4; i++)
        #pragma unroll
        for (int j = 0; j < 4; j++)
            #pragma unroll
            for (int q = 0; q < 4; q++) acc[i][j][q] = 0.0f;

    const int T = K / BK;

    auto load_stage = [&](int s, int k0) {
        #pragma unroll
        for (int g = 0; g < 4; g++)
            CP16(sAbase[s] + (uint32_t)(g * 32 * LDA * 2),
                 gA + (size_t)(g * 32) * lda + k0);
        #pragma unroll
        for (int g = 0; g < 4; g++)
            CP16(sBbase[s] + (uint32_t)(g * 32 * LDA * 2),
                 gB + (size_t)(g * 32) * ldb + k0);
        CPCOMMIT();
    };

    load_stage(0, 0);
    load_stage(1, BK);

    uint32_t af[2][4][4], bq[2][2][4];

    int st = 0;
    for (int t = 0; t < T; t++) {
        if (t + 1 < T) CPWAIT1(); else CPWAIT0();
        __syncthreads();

        if (t + 2 < T) {
            int ns = st + 2; if (ns >= ST) ns -= ST;
            load_stage(ns, (t + 2) * BK);
        }

        // fragment set 0 for kk=0
        #pragma unroll
        for (int i = 0; i < 4; i++)
            ldsm_x4(af[0][i], aBase[st] + (uint32_t)((16 * i * LDA) * 2));
        #pragma unroll
        for (int j16 = 0; j16 < 2; j16++)
            ldsm_x4(bq[0][j16], bBase[st] + (uint32_t)((16 * j16 * LDA) * 2));

        int cur = 0;
        #pragma unroll
        for (int kk = 0; kk < BK; kk += 16) {
            const int nxt = cur ^ 1;
            if (kk + 16 < BK) {       // prefetch next slab's fragments
                #pragma unroll
                for (int i = 0; i < 4; i++)
                    ldsm_x4(af[nxt][i], aBase[st] + (uint32_t)((16 * i * LDA + kk + 16) * 2));
                #pragma unroll
                for (int j16 = 0; j16 < 2; j16++)
                    ldsm_x4(bq[nxt][j16], bBase[st] + (uint32_t)((16 * j16 * LDA + kk + 16) * 2));
            }
            #pragma unroll
            for (int i = 0; i < 4; i++)
                #pragma unroll
                for (int j = 0; j < 4; j++)
                    mma_bf16(acc[i][j], af[cur][i], &bq[cur][j >> 1][(j & 1) * 2]);
            cur = nxt;
        }
        if (++st == ST) st = 0;
    }

    if (MODE == 0) {
        // bias + leaky, bf16 store
        #pragma unroll
        for (int i = 0; i < 4; i++) {
            #pragma unroll
            for (int j = 0; j < 4; j++) {
                const int n0 = bn + wn + 8 * j + c * 2;
                const float bi0 = __ldg(&bias[n0]);
                const float bi1 = __ldg(&bias[n0 + 1]);
                #pragma unroll
                for (int h = 0; h < 2; h++) {
                    const int m = bm + wm + 16 * i + r + 8 * h;
                    float v0 = acc[i][j][2 * h + 0] + bi0;
                    float v1 = acc[i][j][2 * h + 1] + bi1;
                    v0 = (v0 >= 0.0f) ? v0 : 0.01f * v0;
                    v1 = (v1 >= 0.0f) ? v1 : 0.01f * v1;
                    __nv_bfloat162 o = make_bfloat162(__float2bfloat16_rn(v0),
                                                      __float2bfloat16_rn(v1));
                    *reinterpret_cast<__nv_bfloat162*>(
                        &((__nv_bfloat16*)Cv)[(size_t)m * ldc + n0]) = o;
                }
            }
        }
    } else {
        // fused layer-3: s[m] = sum_n leaky(acc+bias) * w4[n] over this warp's N
        float s[4][2];
        #pragma unroll
        for (int i = 0; i < 4; i++) { s[i][0] = 0.0f; s[i][1] = 0.0f; }
        #pragma unroll
        for (int j = 0; j < 4; j++) {
            const int n0 = bn + wn + 8 * j + c * 2;
            const float bi0 = __ldg(&bias[n0]);
            const float bi1 = __ldg(&bias[n0 + 1]);
            const float w0  = __ldg(&w4[n0]);
            const float w1  = __ldg(&w4[n0 + 1]);
            #pragma unroll
            for (int i = 0; i < 4; i++)
                #pragma unroll
                for (int h = 0; h < 2; h++) {
                    float v0 = acc[i][j][2 * h + 0] + bi0;
                    float v1 = acc[i][j][2 * h + 1] + bi1;
                    v0 = (v0 >= 0.0f) ? v0 : 0.01f * v0;
                    v1 = (v1 >= 0.0f) ? v1 : 0.01f * v1;
                    s[i][h] += v0 * w0 + v1 * w1;
                }
        }
        // quad reduce across c (lanes r*4 + c)
        #pragma unroll
        for (int i = 0; i < 4; i++)
            #pragma unroll
            for (int h = 0; h < 2; h++) {
                s[i][h] += __shfl_xor_sync(0xFFFFFFFFu, s[i][h], 1);
                s[i][h] += __shfl_xor_sync(0xFFFFFFFFu, s[i][h], 2);
            }
        if (c == 0) {
            const int p = blockIdx.x * 4 + (warp >> 1);
            #pragma unroll
            for (int i = 0; i < 4; i++)
                #pragma unroll
                for (int h = 0; h < 2; h++) {
                    const int m = bm + wm + 16 * i + r + 8 * h;
                    zp[(size_t)p * BB + m] = s[i][h];
                }
        }
    }
}

// ---------------- final: out = sigmoid(sum zp + b4 + 32*wide) ---------------
__global__ __launch_bounds__(256) void final_kernel(
    const float* __restrict__ zp, const float* __restrict__ b4,
    const float* __restrict__ wide, float* __restrict__ out)
{
    const int row = blockIdx.x * 256 + threadIdx.x;
    float z = b4[0] + (float)EE * wide[row];
    #pragma unroll
    for (int p = 0; p < 8; p++)
        z += zp[(size_t)p * BB + row];
    out[row] = 1.0f / (1.0f + expf(-z));
}

// ---------------- launch ----------------------------------------------------
extern "C" void kernel_launch(void* const* d_in, const int* in_sizes, int n_in,
                              void* d_out, int out_size)
{
    const int*   oh_i  = (const int*)  d_in[0];
    const float* oh_x  = (const float*)d_in[1];
    const int*   mi1   = (const int*)  d_in[2];
    const float* mx1   = (const float*)d_in[3];
    const int*   mi2   = (const int*)  d_in[4];
    const float* mx2   = (const float*)d_in[5];
    const float* ctns  = (const float*)d_in[6];
    const float* wideT = (const float*)d_in[7];
    const float* deepT = (const float*)d_in[8];
    const float* w2    = (const float*)d_in[9];
    const float* b2    = (const float*)d_in[10];
    const float* w3    = (const float*)d_in[11];
    const float* b3    = (const float*)d_in[12];
    const float* w4    = (const float*)d_in[13];
    const float* b4    = (const float*)d_in[14];
    float* out = (float*)d_out;

    __nv_bfloat16 *X, *W2p, *W3r, *H1;
    float *zp, *wide;
    cudaGetSymbolAddress((void**)&X,    g_X);
    cudaGetSymbolAddress((void**)&W2p,  g_W2p);
    cudaGetSymbolAddress((void**)&W3r,  g_W3r);
    cudaGetSymbolAddress((void**)&H1,   g_H1);
    cudaGetSymbolAddress((void**)&zp,   g_zp);
    cudaGetSymbolAddress((void**)&wide, g_wide);

    const int SMEM = 3 * (128 + 128) * 72 * 2;   // 110592 bytes
    static int attr_done = 0;
    if (!attr_done) {
        cudaFuncSetAttribute(bf16_gemm<0>,
                             cudaFuncAttributeMaxDynamicSharedMemorySize, SMEM);
        cudaFuncSetAttribute(bf16_gemm<1>,
                             cudaFuncAttributeMaxDynamicSharedMemorySize, SMEM);
        attr_done = 1;
    }

    // fused gather + weight prep
    gather_kernel<<<BB + D1 + D2, 128>>>(oh_i, oh_x, mi1, mx1, mi2, mx2, ctns,
                                         wideT, deepT, w2, w3,
                                         X, wide, W2p, W3r);

    // layer 1: [B,960] x [512,960]^T -> H1[B,512] bf16
    bf16_gemm<0><<<dim3(D1 / 128, BB / 128), 256, SMEM>>>(
        X, XS, W2p, XS, b2, (void*)H1, D1, XS, nullptr, nullptr);

    // layer 2 + layer 3 (fused): [B,512] x [256,512]^T -> zp[8][B]
    bf16_gemm<1><<<dim3(D2 / 128, BB / 128), 256, SMEM>>>(
        H1, D1, W3r, D1, b3, nullptr, D2, D1, w4, zp);

    // sigmoid( sum(zp) + b4 + 32*wide )
    final_kernel<<<BB / 256, 256>>>(zp, b4, wide, out);
}